// round 10
// baseline (speedup 1.0000x reference)
#include <cuda_runtime.h>
#include <math.h>

#define BSZ   128
#define T     250
#define INDIM 700
#define INP   704
#define H     512
#define NOUT  20
#define HB    (H*BSZ)

#define FIRE_OFF (BSZ*T*NOUT)      /* 640000 */
#define HID_OFF  (FIRE_OFF + 1)

// ---------------- device scratch (static, no allocations) ----------------
__device__ __align__(16) float g_xT  [(size_t)T*INP*BSZ];   // x transposed [t][i][b]
__device__ __align__(16) float g_W1T [INP*H];               // W1 transposed [i][j]
__device__ __align__(16) float g_xw1 [(size_t)T*H*BSZ];     // (x@W1^T)+b_i2h1, [t][j][b]
__device__ __align__(16) float g_m3h [(size_t)T*H*BSZ];     // m3 history [t][j][b]
__device__ __align__(16) float g_s1[2][HB];                 // spikes ping-pong [j][b]
__device__ __align__(16) float g_s2[2][HB];
__device__ __align__(16) float g_s3[2][HB];
__device__ __align__(16) float g_m1[HB], g_m2[HB], g_m3[HB];
__device__ __align__(16) float g_b1[HB], g_b2[HB], g_b3[HB];

// ALIF update with LLVM FPOpFusion::Fast-style contraction (XLA:CPU JIT):
//   b   = fma(ro, b, (1-ro)*s)           [(1-ro)*s exact: s in {0,1}]
//   Bth = fma(1.8, b, 0.01)
//   mem = fma(-Bth, s, fma(mem, al, (1-al)*h))
//   s   = (mem - Bth) > 0
#define ALIF(mm, ss, bb, hh, al, omal, rr, omrr) do {                      \
    bb = __fmaf_rn(rr, bb, __fmul_rn(omrr, ss));                           \
    float Bth_ = __fmaf_rn(1.8f, bb, 0.01f);                               \
    mm = __fmaf_rn(-Bth_, ss, __fmaf_rn(mm, al, __fmul_rn(omal, hh)));     \
    ss = (__fsub_rn(mm, Bth_) > 0.0f) ? 1.0f : 0.0f;                       \
} while (0)

// XLA:CPU GenerateVF32Exp (Cephes/Eigen pexp) with llvm.fmuladd -> FMA.
// Proven bit-equal to correctly-rounded exp on the tau input range (round 8).
__device__ __forceinline__ float exp_xla_fma(float v) {
    float x = fminf(v, 88.3762626647950f);
    x = fmaxf(x, -88.3762626647949f);
    float fx = floorf(__fmaf_rn(x, 1.44269504088896341f, 0.5f));
    float tmp = __fmul_rn(fx, 0.693359375f);
    float z   = __fmul_rn(fx, -2.12194440e-4f);
    x = __fsub_rn(x, tmp);
    x = __fsub_rn(x, z);
    z = __fmul_rn(x, x);
    float y = 1.9875691500E-4f;
    y = __fmaf_rn(y, x, 1.3981999507E-3f);
    y = __fmaf_rn(y, x, 8.3334519073E-3f);
    y = __fmaf_rn(y, x, 4.1665795894E-2f);
    y = __fmaf_rn(y, x, 1.6666665459E-1f);
    y = __fmaf_rn(y, x, 5.0000001201E-1f);
    y = __fmaf_rn(y, z, x);
    y = __fadd_rn(y, 1.0f);
    int n = (int)fx;
    return __fmul_rn(y, __int_as_float((n + 127) << 23));
}

// ---------------- kernel: transpose x -> g_xT [t][i][b] -------------------
__global__ void k_tr(const float* __restrict__ x) {
    __shared__ float tile[32][33];
    int i0 = blockIdx.x * 32, b0 = blockIdx.y * 32, t = blockIdx.z;
    int tx = threadIdx.x, ty = threadIdx.y;
    int i = i0 + tx;
#pragma unroll
    for (int r = 0; r < 4; r++) {
        int b = b0 + ty + r*8;
        float v = 0.0f;
        if (i < INDIM) v = x[((size_t)b*T + t)*INDIM + i];
        tile[ty + r*8][tx] = v;
    }
    __syncthreads();
#pragma unroll
    for (int r = 0; r < 4; r++) {
        int il = ty + r*8;
        g_xT[((size_t)t*INP + i0 + il)*BSZ + b0 + tx] = tile[tx][il];
    }
}

// ---------------- kernel: transpose W1 -> g_W1T ---------------------------
__global__ void k_w1t(const float* __restrict__ W1) {
    int idx = blockIdx.x * 256 + threadIdx.x;
    if (idx < INP*H) {
        int i = idx >> 9, j = idx & 511;
        g_W1T[idx] = (i < INDIM) ? W1[j*INDIM + i] : 0.0f;
    }
}

// ---------------- kernel: init states -------------------------------------
__global__ void k_init() {
    int idx = blockIdx.x * 256 + threadIdx.x;
    if (idx < HB) {
        g_s1[0][idx] = 0.0f; g_s2[0][idx] = 0.0f; g_s3[0][idx] = 0.0f;
        g_m1[idx] = 0.0f;    g_m2[idx] = 0.0f;    g_m3[idx] = 0.0f;
        g_b1[idx] = 0.01f;   g_b2[idx] = 0.01f;   g_b3[idx] = 0.01f;
    }
}

// ---------------- kernel: xw1[t][j][b] = (x@W1^T ascending-k chain)+b_i2h1
__global__ __launch_bounds__(256) void k_xw1(const float* __restrict__ b1) {
    __shared__ __align__(16) float xs[8*128];
    __shared__ __align__(16) float ws[8*128];
    int jg = blockIdx.x, t = blockIdx.y;
    int tid = threadIdx.x;
    int tx = tid & 15, ty = tid >> 4;

    float acc[8][8];
#pragma unroll
    for (int i = 0; i < 8; i++)
#pragma unroll
        for (int jx = 0; jx < 8; jx++) acc[i][jx] = 0.0f;

    for (int k0 = 0; k0 < INP; k0 += 8) {
#pragma unroll
        for (int r = 0; r < 4; r++) {
            int lin = r*256 + tid;
            int kk = lin >> 7, c = lin & 127;
            xs[lin] = g_xT[((size_t)t*INP + k0 + kk)*BSZ + c];
            ws[lin] = g_W1T[(k0 + kk)*H + jg*128 + c];
        }
        __syncthreads();
#pragma unroll
        for (int kk = 0; kk < 8; kk++) {
            float4 x0 = *(const float4*)&xs[kk*128 + tx*8];
            float4 x1 = *(const float4*)&xs[kk*128 + tx*8 + 4];
            float4 w0 = *(const float4*)&ws[kk*128 + ty*8];
            float4 w1 = *(const float4*)&ws[kk*128 + ty*8 + 4];
            float xf[8] = {x0.x,x0.y,x0.z,x0.w,x1.x,x1.y,x1.z,x1.w};
            float wf[8] = {w0.x,w0.y,w0.z,w0.w,w1.x,w1.y,w1.z,w1.w};
#pragma unroll
            for (int i = 0; i < 8; i++)
#pragma unroll
                for (int jx = 0; jx < 8; jx++)
                    acc[i][jx] = __fmaf_rn(wf[i], xf[jx], acc[i][jx]);
        }
        __syncthreads();
    }
#pragma unroll
    for (int i = 0; i < 8; i++) {
        int jcol = jg*128 + ty*8 + i;
        float bias = __ldg(&b1[jcol]);
#pragma unroll
        for (int jx = 0; jx < 8; jx++)
            g_xw1[((size_t)t*H + jcol)*BSZ + tx*8 + jx] =
                __fadd_rn(acc[i][jx], bias);
    }
}

// ---------------- per-step layer kernels -----------------------------------
// 128 blocks x 256 threads; jj = tid>>6 (4 neurons/block), bt = tid&63.

__global__ __launch_bounds__(256) void k_l1(int t,
        const float* __restrict__ Wh1, const float* __restrict__ bh1,
        const float* __restrict__ tm, const float* __restrict__ ta) {
    int jj = threadIdx.x >> 6, bt = threadIdx.x & 63;
    int j = blockIdx.x*4 + jj;
    int p = t & 1, q = p ^ 1;
    float al = exp_xla_fma(__fdiv_rn(-1.0f, __ldg(&tm[j])));
    float ro = exp_xla_fma(__fdiv_rn(-1.0f, __ldg(&ta[j])));
    float omal = __fsub_rn(1.0f, al), omro = __fsub_rn(1.0f, ro);
    const float* __restrict__ w = Wh1 + j*H;

    // recurrent matmul: single ascending-k FMA chain from 0
    float r0 = 0.0f, r1 = 0.0f;
    const float2* sp = (const float2*)g_s1[p] + bt;
#pragma unroll 8
    for (int k = 0; k < H; k++) {
        float2 s = sp[(size_t)k*64];
        float wk = __ldg(&w[k]);
        r0 = __fmaf_rn(s.x, wk, r0);
        r1 = __fmaf_rn(s.y, wk, r1);
    }
    // h = ((x@W1^T + b_i2h1) + rec) + b_h2h1
    size_t xb = ((size_t)t*H + j)*BSZ + 2*bt;
    float bh = __ldg(&bh1[j]);
    float a0 = __fadd_rn(__fadd_rn(g_xw1[xb],     r0), bh);
    float a1 = __fadd_rn(__fadd_rn(g_xw1[xb + 1], r1), bh);

    int idx = j*BSZ + 2*bt;
    float m0 = g_m1[idx], m1v = g_m1[idx+1];
    float b0 = g_b1[idx], b1v = g_b1[idx+1];
    float s0 = g_s1[p][idx], s1v = g_s1[p][idx+1];
    ALIF(m0,  s0,  b0,  a0, al, omal, ro, omro);
    ALIF(m1v, s1v, b1v, a1, al, omal, ro, omro);
    g_m1[idx] = m0;  g_m1[idx+1] = m1v;
    g_b1[idx] = b0;  g_b1[idx+1] = b1v;
    g_s1[q][idx] = s0; g_s1[q][idx+1] = s1v;
}

__global__ __launch_bounds__(256) void k_l2(int t,
        const float* __restrict__ Wi, const float* __restrict__ Wh,
        const float* __restrict__ bi, const float* __restrict__ bh,
        const float* __restrict__ tm, const float* __restrict__ ta) {
    int jj = threadIdx.x >> 6, bt = threadIdx.x & 63;
    int j = blockIdx.x*4 + jj;
    int p = t & 1, q = p ^ 1;
    float al = exp_xla_fma(__fdiv_rn(-1.0f, __ldg(&tm[j])));
    float ro = exp_xla_fma(__fdiv_rn(-1.0f, __ldg(&ta[j])));
    float omal = __fsub_rn(1.0f, al), omro = __fsub_rn(1.0f, ro);
    const float* __restrict__ wi = Wi + j*H;
    const float* __restrict__ wh = Wh + j*H;

    // two independent ascending-k chains, each from 0
    float ri0 = 0.0f, ri1 = 0.0f, rh0 = 0.0f, rh1 = 0.0f;
    const float2* spn = (const float2*)g_s1[q] + bt;   // new s1
    const float2* spo = (const float2*)g_s2[p] + bt;   // old s2
#pragma unroll 4
    for (int k = 0; k < H; k++) {
        float2 u = spn[(size_t)k*64];
        float2 v = spo[(size_t)k*64];
        float wa = __ldg(&wi[k]), wb = __ldg(&wh[k]);
        ri0 = __fmaf_rn(u.x, wa, ri0);
        ri1 = __fmaf_rn(u.y, wa, ri1);
        rh0 = __fmaf_rn(v.x, wb, rh0);
        rh1 = __fmaf_rn(v.y, wb, rh1);
    }
    // h = (((s1@Wi^T) + bi) + (s2@Wh^T)) + bh
    float bv = __ldg(&bi[j]), hv = __ldg(&bh[j]);
    float a0 = __fadd_rn(__fadd_rn(__fadd_rn(ri0, bv), rh0), hv);
    float a1 = __fadd_rn(__fadd_rn(__fadd_rn(ri1, bv), rh1), hv);

    int idx = j*BSZ + 2*bt;
    float m0 = g_m2[idx], m1v = g_m2[idx+1];
    float b0 = g_b2[idx], b1v = g_b2[idx+1];
    float s0 = g_s2[p][idx], s1v = g_s2[p][idx+1];
    ALIF(m0,  s0,  b0,  a0, al, omal, ro, omro);
    ALIF(m1v, s1v, b1v, a1, al, omal, ro, omro);
    g_m2[idx] = m0;  g_m2[idx+1] = m1v;
    g_b2[idx] = b0;  g_b2[idx+1] = b1v;
    g_s2[q][idx] = s0; g_s2[q][idx+1] = s1v;
}

__global__ __launch_bounds__(256) void k_l3(int t,
        const float* __restrict__ Wi, const float* __restrict__ Wh,
        const float* __restrict__ bi, const float* __restrict__ bh,
        const float* __restrict__ tm, const float* __restrict__ ta,
        float* __restrict__ dout) {
    int jj = threadIdx.x >> 6, bt = threadIdx.x & 63;
    int j = blockIdx.x*4 + jj;
    int p = t & 1, q = p ^ 1;
    float al = exp_xla_fma(__fdiv_rn(-1.0f, __ldg(&tm[j])));
    float ro = exp_xla_fma(__fdiv_rn(-1.0f, __ldg(&ta[j])));
    float omal = __fsub_rn(1.0f, al), omro = __fsub_rn(1.0f, ro);
    const float* __restrict__ wi = Wi + j*H;
    const float* __restrict__ wh = Wh + j*H;

    float ri0 = 0.0f, ri1 = 0.0f, rh0 = 0.0f, rh1 = 0.0f;
    const float2* spn = (const float2*)g_s2[q] + bt;   // new s2
    const float2* spo = (const float2*)g_s3[p] + bt;   // old s3
#pragma unroll 4
    for (int k = 0; k < H; k++) {
        float2 u = spn[(size_t)k*64];
        float2 v = spo[(size_t)k*64];
        float wa = __ldg(&wi[k]), wb = __ldg(&wh[k]);
        ri0 = __fmaf_rn(u.x, wa, ri0);
        ri1 = __fmaf_rn(u.y, wa, ri1);
        rh0 = __fmaf_rn(v.x, wb, rh0);
        rh1 = __fmaf_rn(v.y, wb, rh1);
    }
    float bv = __ldg(&bi[j]), hv = __ldg(&bh[j]);
    float a0 = __fadd_rn(__fadd_rn(__fadd_rn(ri0, bv), rh0), hv);
    float a1 = __fadd_rn(__fadd_rn(__fadd_rn(ri1, bv), rh1), hv);

    int idx = j*BSZ + 2*bt;
    float m0 = g_m3[idx], m1v = g_m3[idx+1];
    float b0 = g_b3[idx], b1v = g_b3[idx+1];
    float s0 = g_s3[p][idx], s1v = g_s3[p][idx+1];
    ALIF(m0,  s0,  b0,  a0, al, omal, ro, omro);
    ALIF(m1v, s1v, b1v, a1, al, omal, ro, omro);
    g_m3[idx] = m0;  g_m3[idx+1] = m1v;
    g_b3[idx] = b0;  g_b3[idx+1] = b1v;
    g_s3[q][idx] = s0; g_s3[q][idx+1] = s1v;

    g_m3h[((size_t)t*H + j)*BSZ + 2*bt]     = m0;
    g_m3h[((size_t)t*H + j)*BSZ + 2*bt + 1] = m1v;
    dout[HID_OFF + ((size_t)(2*bt    )*T + t)*H + j] = s0;
    dout[HID_OFF + ((size_t)(2*bt + 1)*T + t)*H + j] = s1v;
}

// ---------------- kernel: output = (m3@Wo^T chain from 0) + bo ------------
__global__ __launch_bounds__(128) void k_out(const float* __restrict__ Wo,
                                             const float* __restrict__ bo,
                                             float* __restrict__ dout) {
    int t = blockIdx.x, b = threadIdx.x;
    float acc[NOUT];
#pragma unroll
    for (int o = 0; o < NOUT; o++) acc[o] = 0.0f;
    const float* mp = &g_m3h[(size_t)t*H*BSZ + b];
    for (int k = 0; k < H; k++) {
        float v = mp[(size_t)k*BSZ];
#pragma unroll
        for (int o = 0; o < NOUT; o++)
            acc[o] = __fmaf_rn(v, __ldg(&Wo[o*H + k]), acc[o]);
    }
#pragma unroll
    for (int o = 0; o < NOUT; o++)
        dout[((size_t)b*T + t)*NOUT + o] = __fadd_rn(acc[o], __ldg(&bo[o]));
}

// ---------------- kernel: fire rate from final spikes (buffers [0]) -------
__global__ void k_fire(float* __restrict__ dout) {
    __shared__ float red[32];
    int tid = threadIdx.x;
    float c = 0.0f;
    for (int i = tid; i < HB; i += 1024)
        c += g_s1[0][i] + g_s2[0][i] + g_s3[0][i];
#pragma unroll
    for (int o = 16; o > 0; o >>= 1) c += __shfl_xor_sync(0xffffffffu, c, o);
    if ((tid & 31) == 0) red[tid >> 5] = c;
    __syncthreads();
    if (tid == 0) {
        float s = 0.0f;
#pragma unroll
        for (int i = 0; i < 32; i++) s += red[i];
        dout[FIRE_OFF] = s / 196608.0f;
    }
}

// ---------------- launch ---------------------------------------------------
extern "C" void kernel_launch(void* const* d_in, const int* in_sizes, int n_in,
                              void* d_out, int out_size) {
    const float* x      = (const float*)d_in[0];
    const float* W_i2h1 = (const float*)d_in[1];  const float* b_i2h1 = (const float*)d_in[2];
    const float* W_h2h1 = (const float*)d_in[3];  const float* b_h2h1 = (const float*)d_in[4];
    const float* W_i2h2 = (const float*)d_in[5];  const float* b_i2h2 = (const float*)d_in[6];
    const float* W_h2h2 = (const float*)d_in[7];  const float* b_h2h2 = (const float*)d_in[8];
    const float* W_i2h3 = (const float*)d_in[9];  const float* b_i2h3 = (const float*)d_in[10];
    const float* W_h2h3 = (const float*)d_in[11]; const float* b_h2h3 = (const float*)d_in[12];
    const float* W_h2o  = (const float*)d_in[13]; const float* b_h2o  = (const float*)d_in[14];
    const float* ta1 = (const float*)d_in[15];
    const float* ta2 = (const float*)d_in[16];
    const float* ta3 = (const float*)d_in[17];
    const float* tm1 = (const float*)d_in[18];
    const float* tm2 = (const float*)d_in[19];
    const float* tm3 = (const float*)d_in[20];
    float* out = (float*)d_out;

    k_tr  <<<dim3(22, 4, 250), dim3(32, 8)>>>(x);
    k_w1t <<<(INP*H + 255)/256, 256>>>(W_i2h1);
    k_init<<<(HB + 255)/256, 256>>>();
    k_xw1 <<<dim3(4, 250), 256>>>(b_i2h1);

    for (int t = 0; t < T; t++) {
        k_l1<<<128, 256>>>(t, W_h2h1, b_h2h1, tm1, ta1);
        k_l2<<<128, 256>>>(t, W_i2h2, W_h2h2, b_i2h2, b_h2h2, tm2, ta2);
        k_l3<<<128, 256>>>(t, W_i2h3, W_h2h3, b_i2h3, b_h2h3, tm3, ta3, out);
    }

    k_out <<<250, 128>>>(W_h2o, b_h2o, out);
    k_fire<<<1, 1024>>>(out);
}

// round 11
// speedup vs baseline: 2.1933x; 2.1933x over previous
#include <cuda_runtime.h>
#include <math.h>

#define BSZ   128
#define T     250
#define INDIM 700
#define INP   704
#define H     512
#define NOUT  20
#define HB    (H*BSZ)
#define NCTA  128

#define FIRE_OFF (BSZ*T*NOUT)      /* 640000 */
#define HID_OFF  (FIRE_OFF + 1)

// ---------------- device scratch (static, no allocations) ----------------
__device__ __align__(16) float g_xT  [(size_t)T*INP*BSZ];   // x transposed [t][i][b]
__device__ __align__(16) float g_W1T [INP*H];               // W1 transposed [i][j]
__device__ __align__(16) float g_xw1 [(size_t)T*H*BSZ];     // (x@W1^T)+b_i2h1, [t][j][b]
__device__ __align__(16) float g_m3h [(size_t)T*H*BSZ];     // m3 history [t][j][b]
__device__ __align__(16) float g_s1[2][HB];                 // spikes ping-pong [j][b]
__device__ __align__(16) float g_s2[2][HB];
__device__ __align__(16) float g_s3[2][HB];
__device__ unsigned g_barc;                                 // monotonic barrier counter

// ALIF update with LLVM FPOpFusion::Fast-style contraction (VALIDATED r9).
#define ALIF(mm, ss, bb, hh, al, omal, rr, omrr) do {                      \
    bb = __fmaf_rn(rr, bb, __fmul_rn(omrr, ss));                           \
    float Bth_ = __fmaf_rn(1.8f, bb, 0.01f);                               \
    mm = __fmaf_rn(-Bth_, ss, __fmaf_rn(mm, al, __fmul_rn(omal, hh)));     \
    ss = (__fsub_rn(mm, Bth_) > 0.0f) ? 1.0f : 0.0f;                       \
} while (0)

// XLA:CPU GenerateVF32Exp (VALIDATED r9)
__device__ __forceinline__ float exp_xla_fma(float v) {
    float x = fminf(v, 88.3762626647950f);
    x = fmaxf(x, -88.3762626647949f);
    float fx = floorf(__fmaf_rn(x, 1.44269504088896341f, 0.5f));
    float tmp = __fmul_rn(fx, 0.693359375f);
    float z   = __fmul_rn(fx, -2.12194440e-4f);
    x = __fsub_rn(x, tmp);
    x = __fsub_rn(x, z);
    z = __fmul_rn(x, x);
    float y = 1.9875691500E-4f;
    y = __fmaf_rn(y, x, 1.3981999507E-3f);
    y = __fmaf_rn(y, x, 8.3334519073E-3f);
    y = __fmaf_rn(y, x, 4.1665795894E-2f);
    y = __fmaf_rn(y, x, 1.6666665459E-1f);
    y = __fmaf_rn(y, x, 5.0000001201E-1f);
    y = __fmaf_rn(y, z, x);
    y = __fadd_rn(y, 1.0f);
    int n = (int)fx;
    return __fmul_rn(y, __int_as_float((n + 127) << 23));
}

// grid barrier: monotonic counter (no reset; ends each run at a multiple of NCTA)
__device__ __forceinline__ void gbar() {
    __syncthreads();
    if (threadIdx.x == 0) {
        __threadfence();
        unsigned r   = atomicAdd(&g_barc, 1u) + 1u;
        unsigned tgt = ((r + NCTA - 1u) / NCTA) * NCTA;
        while (*((volatile unsigned*)&g_barc) < tgt) { }
        __threadfence();
    }
    __syncthreads();
}

// ---------------- kernel: transpose x -> g_xT [t][i][b] -------------------
__global__ void k_tr(const float* __restrict__ x) {
    __shared__ float tile[32][33];
    int i0 = blockIdx.x * 32, b0 = blockIdx.y * 32, t = blockIdx.z;
    int tx = threadIdx.x, ty = threadIdx.y;
    int i = i0 + tx;
#pragma unroll
    for (int r = 0; r < 4; r++) {
        int b = b0 + ty + r*8;
        float v = 0.0f;
        if (i < INDIM) v = x[((size_t)b*T + t)*INDIM + i];
        tile[ty + r*8][tx] = v;
    }
    __syncthreads();
#pragma unroll
    for (int r = 0; r < 4; r++) {
        int il = ty + r*8;
        g_xT[((size_t)t*INP + i0 + il)*BSZ + b0 + tx] = tile[tx][il];
    }
}

// ---------------- kernel: transpose W1 -> g_W1T ---------------------------
__global__ void k_w1t(const float* __restrict__ W1) {
    int idx = blockIdx.x * 256 + threadIdx.x;
    if (idx < INP*H) {
        int i = idx >> 9, j = idx & 511;
        g_W1T[idx] = (i < INDIM) ? W1[j*INDIM + i] : 0.0f;
    }
}

// ---------------- kernel: init spike buffers ------------------------------
__global__ void k_init() {
    int idx = blockIdx.x * 256 + threadIdx.x;
    if (idx < HB) {
        g_s1[0][idx] = 0.0f; g_s2[0][idx] = 0.0f; g_s3[0][idx] = 0.0f;
    }
}

// ---------------- kernel: xw1[t][j][b] = (x@W1^T ascending-k chain)+b_i2h1
__global__ __launch_bounds__(256) void k_xw1(const float* __restrict__ b1) {
    __shared__ __align__(16) float xs[8*128];
    __shared__ __align__(16) float ws[8*128];
    int jg = blockIdx.x, t = blockIdx.y;
    int tid = threadIdx.x;
    int tx = tid & 15, ty = tid >> 4;

    float acc[8][8];
#pragma unroll
    for (int i = 0; i < 8; i++)
#pragma unroll
        for (int jx = 0; jx < 8; jx++) acc[i][jx] = 0.0f;

    for (int k0 = 0; k0 < INP; k0 += 8) {
#pragma unroll
        for (int r = 0; r < 4; r++) {
            int lin = r*256 + tid;
            int kk = lin >> 7, c = lin & 127;
            xs[lin] = g_xT[((size_t)t*INP + k0 + kk)*BSZ + c];
            ws[lin] = g_W1T[(k0 + kk)*H + jg*128 + c];
        }
        __syncthreads();
#pragma unroll
        for (int kk = 0; kk < 8; kk++) {
            float4 x0 = *(const float4*)&xs[kk*128 + tx*8];
            float4 x1 = *(const float4*)&xs[kk*128 + tx*8 + 4];
            float4 w0 = *(const float4*)&ws[kk*128 + ty*8];
            float4 w1 = *(const float4*)&ws[kk*128 + ty*8 + 4];
            float xf[8] = {x0.x,x0.y,x0.z,x0.w,x1.x,x1.y,x1.z,x1.w};
            float wf[8] = {w0.x,w0.y,w0.z,w0.w,w1.x,w1.y,w1.z,w1.w};
#pragma unroll
            for (int i = 0; i < 8; i++)
#pragma unroll
                for (int jx = 0; jx < 8; jx++)
                    acc[i][jx] = __fmaf_rn(wf[i], xf[jx], acc[i][jx]);
        }
        __syncthreads();
    }
#pragma unroll
    for (int i = 0; i < 8; i++) {
        int jcol = jg*128 + ty*8 + i;
        float bias = __ldg(&b1[jcol]);
#pragma unroll
        for (int jx = 0; jx < 8; jx++)
            g_xw1[((size_t)t*H + jcol)*BSZ + tx*8 + jx] =
                __fadd_rn(acc[i][jx], bias);
    }
}

// ---------------- persistent ALIF scan -------------------------------------
// 128 CTAs x 128 threads. CTA owns 4 neurons; thread owns batch column b.
// 3 grid barriers per step. Spikes via L2 (__ldcg/__stcg).
__global__ __launch_bounds__(128) void k_scan(
    const float* __restrict__ Wh1, const float* __restrict__ bh1,
    const float* __restrict__ Wi2, const float* __restrict__ Wh2,
    const float* __restrict__ bi2, const float* __restrict__ bh2,
    const float* __restrict__ Wi3, const float* __restrict__ Wh3,
    const float* __restrict__ bi3, const float* __restrict__ bh3,
    const float* __restrict__ ta1, const float* __restrict__ ta2,
    const float* __restrict__ ta3, const float* __restrict__ tm1,
    const float* __restrict__ tm2, const float* __restrict__ tm3,
    float* __restrict__ dout)
{
    __shared__ float sw[5][4][H];             // 40KB weights for 4 owned neurons
    const int tid = threadIdx.x;
    const int b   = tid;                      // batch column
    const int j0  = blockIdx.x * 4;

    // stage weights
    for (int i = tid; i < 5*4*H; i += 128) {
        int m = i / (4*H), rem = i % (4*H), jl = rem >> 9, k = rem & 511;
        const float* W = (m==0)?Wh1:(m==1)?Wi2:(m==2)?Wh2:(m==3)?Wi3:Wh3;
        sw[m][jl][k] = W[(size_t)(j0 + jl)*H + k];
    }
    __syncthreads();

    // per-neuron constants + biases (hoisted; bit-same expressions as r9)
    float al1[4], ro1[4], omal1[4], omro1[4];
    float al2[4], ro2[4], omal2[4], omro2[4];
    float al3[4], ro3[4], omal3[4], omro3[4];
    float bh1r[4], bi2r[4], bh2r[4], bi3r[4], bh3r[4];
#pragma unroll
    for (int jl = 0; jl < 4; jl++) {
        int j = j0 + jl;
        al1[jl] = exp_xla_fma(__fdiv_rn(-1.0f, __ldg(&tm1[j])));
        ro1[jl] = exp_xla_fma(__fdiv_rn(-1.0f, __ldg(&ta1[j])));
        al2[jl] = exp_xla_fma(__fdiv_rn(-1.0f, __ldg(&tm2[j])));
        ro2[jl] = exp_xla_fma(__fdiv_rn(-1.0f, __ldg(&ta2[j])));
        al3[jl] = exp_xla_fma(__fdiv_rn(-1.0f, __ldg(&tm3[j])));
        ro3[jl] = exp_xla_fma(__fdiv_rn(-1.0f, __ldg(&ta3[j])));
        omal1[jl] = __fsub_rn(1.0f, al1[jl]); omro1[jl] = __fsub_rn(1.0f, ro1[jl]);
        omal2[jl] = __fsub_rn(1.0f, al2[jl]); omro2[jl] = __fsub_rn(1.0f, ro2[jl]);
        omal3[jl] = __fsub_rn(1.0f, al3[jl]); omro3[jl] = __fsub_rn(1.0f, ro3[jl]);
        bh1r[jl] = __ldg(&bh1[j]);
        bi2r[jl] = __ldg(&bi2[j]); bh2r[jl] = __ldg(&bh2[j]);
        bi3r[jl] = __ldg(&bi3[j]); bh3r[jl] = __ldg(&bh3[j]);
    }

    // register-resident ALIF state
    float m1[4], b1s[4], s1r[4];
    float m2[4], b2s[4], s2r[4];
    float m3[4], b3s[4], s3r[4];
#pragma unroll
    for (int jl = 0; jl < 4; jl++) {
        m1[jl]=0.0f; b1s[jl]=0.01f; s1r[jl]=0.0f;
        m2[jl]=0.0f; b2s[jl]=0.01f; s2r[jl]=0.0f;
        m3[jl]=0.0f; b3s[jl]=0.01f; s3r[jl]=0.0f;
    }
    gbar();   // spike buffers (k_init) visible to all CTAs

    for (int t = 0; t < T; t++) {
        const int p = t & 1, q = p ^ 1;
        // ---- layer 1 ----
        {
            float r[4] = {0.0f, 0.0f, 0.0f, 0.0f};
            const float* sp = g_s1[p] + b;
#pragma unroll 8
            for (int k = 0; k < H; k++) {
                float s = __ldcg(&sp[(size_t)k*BSZ]);
#pragma unroll
                for (int jl = 0; jl < 4; jl++)
                    r[jl] = __fmaf_rn(s, sw[0][jl][k], r[jl]);
            }
#pragma unroll
            for (int jl = 0; jl < 4; jl++) {
                int j = j0 + jl;
                float a = __fadd_rn(__fadd_rn(
                    __ldg(&g_xw1[((size_t)t*H + j)*BSZ + b]), r[jl]), bh1r[jl]);
                ALIF(m1[jl], s1r[jl], b1s[jl], a,
                     al1[jl], omal1[jl], ro1[jl], omro1[jl]);
                __stcg(&g_s1[q][(size_t)j*BSZ + b], s1r[jl]);
            }
        }
        gbar();
        // ---- layer 2 ----
        {
            float ri[4] = {0,0,0,0}, rh[4] = {0,0,0,0};
            const float* spn = g_s1[q] + b;
            const float* spo = g_s2[p] + b;
#pragma unroll 4
            for (int k = 0; k < H; k++) {
                float u = __ldcg(&spn[(size_t)k*BSZ]);
                float v = __ldcg(&spo[(size_t)k*BSZ]);
#pragma unroll
                for (int jl = 0; jl < 4; jl++) {
                    ri[jl] = __fmaf_rn(u, sw[1][jl][k], ri[jl]);
                    rh[jl] = __fmaf_rn(v, sw[2][jl][k], rh[jl]);
                }
            }
#pragma unroll
            for (int jl = 0; jl < 4; jl++) {
                int j = j0 + jl;
                float a = __fadd_rn(__fadd_rn(__fadd_rn(ri[jl], bi2r[jl]),
                                              rh[jl]), bh2r[jl]);
                ALIF(m2[jl], s2r[jl], b2s[jl], a,
                     al2[jl], omal2[jl], ro2[jl], omro2[jl]);
                __stcg(&g_s2[q][(size_t)j*BSZ + b], s2r[jl]);
            }
        }
        gbar();
        // ---- layer 3 ----
        {
            float ri[4] = {0,0,0,0}, rh[4] = {0,0,0,0};
            const float* spn = g_s2[q] + b;
            const float* spo = g_s3[p] + b;
#pragma unroll 4
            for (int k = 0; k < H; k++) {
                float u = __ldcg(&spn[(size_t)k*BSZ]);
                float v = __ldcg(&spo[(size_t)k*BSZ]);
#pragma unroll
                for (int jl = 0; jl < 4; jl++) {
                    ri[jl] = __fmaf_rn(u, sw[3][jl][k], ri[jl]);
                    rh[jl] = __fmaf_rn(v, sw[4][jl][k], rh[jl]);
                }
            }
#pragma unroll
            for (int jl = 0; jl < 4; jl++) {
                int j = j0 + jl;
                float a = __fadd_rn(__fadd_rn(__fadd_rn(ri[jl], bi3r[jl]),
                                              rh[jl]), bh3r[jl]);
                ALIF(m3[jl], s3r[jl], b3s[jl], a,
                     al3[jl], omal3[jl], ro3[jl], omro3[jl]);
                __stcg(&g_s3[q][(size_t)j*BSZ + b], s3r[jl]);
                g_m3h[((size_t)t*H + j)*BSZ + b] = m3[jl];
                dout[HID_OFF + ((size_t)b*T + t)*H + j] = s3r[jl];
            }
        }
        gbar();
    }
}

// ---------------- kernel: output = (m3@Wo^T chain from 0) + bo ------------
__global__ __launch_bounds__(128) void k_out(const float* __restrict__ Wo,
                                             const float* __restrict__ bo,
                                             float* __restrict__ dout) {
    int t = blockIdx.x, b = threadIdx.x;
    float acc[NOUT];
#pragma unroll
    for (int o = 0; o < NOUT; o++) acc[o] = 0.0f;
    const float* mp = &g_m3h[(size_t)t*H*BSZ + b];
    for (int k = 0; k < H; k++) {
        float v = mp[(size_t)k*BSZ];
#pragma unroll
        for (int o = 0; o < NOUT; o++)
            acc[o] = __fmaf_rn(v, __ldg(&Wo[o*H + k]), acc[o]);
    }
#pragma unroll
    for (int o = 0; o < NOUT; o++)
        dout[((size_t)b*T + t)*NOUT + o] = __fadd_rn(acc[o], __ldg(&bo[o]));
}

// ---------------- kernel: fire rate from final spikes (buffers [0]) -------
__global__ void k_fire(float* __restrict__ dout) {
    __shared__ float red[32];
    int tid = threadIdx.x;
    float c = 0.0f;
    for (int i = tid; i < HB; i += 1024)
        c += g_s1[0][i] + g_s2[0][i] + g_s3[0][i];
#pragma unroll
    for (int o = 16; o > 0; o >>= 1) c += __shfl_xor_sync(0xffffffffu, c, o);
    if ((tid & 31) == 0) red[tid >> 5] = c;
    __syncthreads();
    if (tid == 0) {
        float s = 0.0f;
#pragma unroll
        for (int i = 0; i < 32; i++) s += red[i];
        dout[FIRE_OFF] = s / 196608.0f;
    }
}

// ---------------- launch ---------------------------------------------------
extern "C" void kernel_launch(void* const* d_in, const int* in_sizes, int n_in,
                              void* d_out, int out_size) {
    const float* x      = (const float*)d_in[0];
    const float* W_i2h1 = (const float*)d_in[1];  const float* b_i2h1 = (const float*)d_in[2];
    const float* W_h2h1 = (const float*)d_in[3];  const float* b_h2h1 = (const float*)d_in[4];
    const float* W_i2h2 = (const float*)d_in[5];  const float* b_i2h2 = (const float*)d_in[6];
    const float* W_h2h2 = (const float*)d_in[7];  const float* b_h2h2 = (const float*)d_in[8];
    const float* W_i2h3 = (const float*)d_in[9];  const float* b_i2h3 = (const float*)d_in[10];
    const float* W_h2h3 = (const float*)d_in[11]; const float* b_h2h3 = (const float*)d_in[12];
    const float* W_h2o  = (const float*)d_in[13]; const float* b_h2o  = (const float*)d_in[14];
    const float* ta1 = (const float*)d_in[15];
    const float* ta2 = (const float*)d_in[16];
    const float* ta3 = (const float*)d_in[17];
    const float* tm1 = (const float*)d_in[18];
    const float* tm2 = (const float*)d_in[19];
    const float* tm3 = (const float*)d_in[20];
    float* out = (float*)d_out;

    k_tr  <<<dim3(22, 4, 250), dim3(32, 8)>>>(x);
    k_w1t <<<(INP*H + 255)/256, 256>>>(W_i2h1);
    k_init<<<(HB + 255)/256, 256>>>();
    k_xw1 <<<dim3(4, 250), 256>>>(b_i2h1);

    k_scan<<<NCTA, 128>>>(W_h2h1, b_h2h1,
                          W_i2h2, W_h2h2, b_i2h2, b_h2h2,
                          W_i2h3, W_h2h3, b_i2h3, b_h2h3,
                          ta1, ta2, ta3, tm1, tm2, tm3, out);

    k_out <<<250, 128>>>(W_h2o, b_h2o, out);
    k_fire<<<1, 1024>>>(out);
}

// round 12
// speedup vs baseline: 6.5246x; 2.9747x over previous
#include <cuda_runtime.h>
#include <math.h>

#define BSZ   128
#define T     250
#define INDIM 700
#define INP   704
#define H     512
#define NOUT  20
#define HB    (H*BSZ)
#define NCTA  128

#define FIRE_OFF (BSZ*T*NOUT)      /* 640000 */
#define HID_OFF  (FIRE_OFF + 1)

// ---------------- device scratch (static, no allocations) ----------------
__device__ __align__(16) float g_xT  [(size_t)T*INP*BSZ];   // x transposed [t][i][b]
__device__ __align__(16) float g_W1T [INP*H];               // W1 transposed [i][j]
__device__ __align__(16) float g_xw1 [(size_t)T*H*BSZ];     // (x@W1^T)+b_i2h1, [t][j][b]
__device__ __align__(16) float g_m3h [(size_t)T*H*BSZ];     // m3 history [t][j][b]
// bit-packed spikes: [slot][b][jg] (byte jg holds spikes of neurons 4jg..4jg+3)
__device__ __align__(16) unsigned char g_pb1[2][BSZ*128];
__device__ __align__(16) unsigned char g_pb2[2][BSZ*128];
__device__ __align__(16) unsigned char g_pb3[2][BSZ*128];
__device__ float    g_cnt;                                  // fire-rate accumulator
__device__ unsigned g_barc;                                 // monotonic barrier counter

// ALIF update with LLVM FPOpFusion::Fast-style contraction (VALIDATED r9/r11).
#define ALIF(mm, ss, bb, hh, al, omal, rr, omrr) do {                      \
    bb = __fmaf_rn(rr, bb, __fmul_rn(omrr, ss));                           \
    float Bth_ = __fmaf_rn(1.8f, bb, 0.01f);                               \
    mm = __fmaf_rn(-Bth_, ss, __fmaf_rn(mm, al, __fmul_rn(omal, hh)));     \
    ss = (__fsub_rn(mm, Bth_) > 0.0f) ? 1.0f : 0.0f;                       \
} while (0)

// XLA:CPU GenerateVF32Exp (VALIDATED r9/r11)
__device__ __forceinline__ float exp_xla_fma(float v) {
    float x = fminf(v, 88.3762626647950f);
    x = fmaxf(x, -88.3762626647949f);
    float fx = floorf(__fmaf_rn(x, 1.44269504088896341f, 0.5f));
    float tmp = __fmul_rn(fx, 0.693359375f);
    float z   = __fmul_rn(fx, -2.12194440e-4f);
    x = __fsub_rn(x, tmp);
    x = __fsub_rn(x, z);
    z = __fmul_rn(x, x);
    float y = 1.9875691500E-4f;
    y = __fmaf_rn(y, x, 1.3981999507E-3f);
    y = __fmaf_rn(y, x, 8.3334519073E-3f);
    y = __fmaf_rn(y, x, 4.1665795894E-2f);
    y = __fmaf_rn(y, x, 1.6666665459E-1f);
    y = __fmaf_rn(y, x, 5.0000001201E-1f);
    y = __fmaf_rn(y, z, x);
    y = __fadd_rn(y, 1.0f);
    int n = (int)fx;
    return __fmul_rn(y, __int_as_float((n + 127) << 23));
}

// grid barrier: monotonic counter
__device__ __forceinline__ void gbar() {
    __syncthreads();
    if (threadIdx.x == 0) {
        __threadfence();
        unsigned r   = atomicAdd(&g_barc, 1u) + 1u;
        unsigned tgt = ((r + NCTA - 1u) / NCTA) * NCTA;
        while (*((volatile unsigned*)&g_barc) < tgt) { }
        __threadfence();
    }
    __syncthreads();
}

// one dot stream over a packed spike vector (128 contiguous bytes at base).
// Bit-exact vs r11: u is the same 0/1 spike value, same fma, ascending k.
__device__ __forceinline__ void dot_stream(const unsigned char* base,
                                           const float (*swm)[4],
                                           float& r0, float& r1,
                                           float& r2, float& r3) {
    const uint4* mp = (const uint4*)base;
    uint4 mq = __ldcg(&mp[0]);
#pragma unroll 1
    for (int wq = 0; wq < 8; wq++) {
        uint4 cur = mq;
        if (wq < 7) mq = __ldcg(&mp[wq + 1]);
        unsigned wds[4] = {cur.x, cur.y, cur.z, cur.w};
#pragma unroll
        for (int wi = 0; wi < 4; wi++) {
            unsigned wd = wds[wi];
#pragma unroll
            for (int d = 0; d < 4; d++) {
#pragma unroll
                for (int c = 0; c < 4; c++) {
                    int k = wq*64 + wi*16 + d*4 + c;
                    float u = (wd & (1u << (8*d + c))) ? 1.0f : 0.0f;
                    float4 wv = *(const float4*)&swm[k][0];
                    r0 = __fmaf_rn(u, wv.x, r0);
                    r1 = __fmaf_rn(u, wv.y, r1);
                    r2 = __fmaf_rn(u, wv.z, r2);
                    r3 = __fmaf_rn(u, wv.w, r3);
                }
            }
        }
    }
}

// ---------------- kernel: transpose x -> g_xT [t][i][b] -------------------
__global__ void k_tr(const float* __restrict__ x) {
    __shared__ float tile[32][33];
    int i0 = blockIdx.x * 32, b0 = blockIdx.y * 32, t = blockIdx.z;
    int tx = threadIdx.x, ty = threadIdx.y;
    int i = i0 + tx;
#pragma unroll
    for (int r = 0; r < 4; r++) {
        int b = b0 + ty + r*8;
        float v = 0.0f;
        if (i < INDIM) v = x[((size_t)b*T + t)*INDIM + i];
        tile[ty + r*8][tx] = v;
    }
    __syncthreads();
#pragma unroll
    for (int r = 0; r < 4; r++) {
        int il = ty + r*8;
        g_xT[((size_t)t*INP + i0 + il)*BSZ + b0 + tx] = tile[tx][il];
    }
}

// ---------------- kernel: transpose W1 -> g_W1T ---------------------------
__global__ void k_w1t(const float* __restrict__ W1) {
    int idx = blockIdx.x * 256 + threadIdx.x;
    if (idx < INP*H) {
        int i = idx >> 9, j = idx & 511;
        g_W1T[idx] = (i < INDIM) ? W1[j*INDIM + i] : 0.0f;
    }
}

// ---------------- kernel: init packed spike buffers + fire counter --------
__global__ void k_init() {
    int idx = blockIdx.x * 256 + threadIdx.x;
    if (idx == 0) g_cnt = 0.0f;
    if (idx < (2*BSZ*128)/4) {
        ((unsigned*)g_pb1)[idx] = 0u;
        ((unsigned*)g_pb2)[idx] = 0u;
        ((unsigned*)g_pb3)[idx] = 0u;
    }
}

// ---------------- kernel: xw1[t][j][b] = (x@W1^T ascending-k chain)+b_i2h1
__global__ __launch_bounds__(256) void k_xw1(const float* __restrict__ b1) {
    __shared__ __align__(16) float xs[8*128];
    __shared__ __align__(16) float ws[8*128];
    int jg = blockIdx.x, t = blockIdx.y;
    int tid = threadIdx.x;
    int tx = tid & 15, ty = tid >> 4;

    float acc[8][8];
#pragma unroll
    for (int i = 0; i < 8; i++)
#pragma unroll
        for (int jx = 0; jx < 8; jx++) acc[i][jx] = 0.0f;

    for (int k0 = 0; k0 < INP; k0 += 8) {
#pragma unroll
        for (int r = 0; r < 4; r++) {
            int lin = r*256 + tid;
            int kk = lin >> 7, c = lin & 127;
            xs[lin] = g_xT[((size_t)t*INP + k0 + kk)*BSZ + c];
            ws[lin] = g_W1T[(k0 + kk)*H + jg*128 + c];
        }
        __syncthreads();
#pragma unroll
        for (int kk = 0; kk < 8; kk++) {
            float4 x0 = *(const float4*)&xs[kk*128 + tx*8];
            float4 x1 = *(const float4*)&xs[kk*128 + tx*8 + 4];
            float4 w0 = *(const float4*)&ws[kk*128 + ty*8];
            float4 w1 = *(const float4*)&ws[kk*128 + ty*8 + 4];
            float xf[8] = {x0.x,x0.y,x0.z,x0.w,x1.x,x1.y,x1.z,x1.w};
            float wf[8] = {w0.x,w0.y,w0.z,w0.w,w1.x,w1.y,w1.z,w1.w};
#pragma unroll
            for (int i = 0; i < 8; i++)
#pragma unroll
                for (int jx = 0; jx < 8; jx++)
                    acc[i][jx] = __fmaf_rn(wf[i], xf[jx], acc[i][jx]);
        }
        __syncthreads();
    }
#pragma unroll
    for (int i = 0; i < 8; i++) {
        int jcol = jg*128 + ty*8 + i;
        float bias = __ldg(&b1[jcol]);
#pragma unroll
        for (int jx = 0; jx < 8; jx++)
            g_xw1[((size_t)t*H + jcol)*BSZ + tx*8 + jx] =
                __fadd_rn(acc[i][jx], bias);
    }
}

// ---------------- persistent ALIF scan (bit-packed spikes) -----------------
// 128 CTAs x 128 threads. CTA owns 4 neurons (one packed byte); thread owns b.
__global__ __launch_bounds__(128) void k_scan(
    const float* __restrict__ Wh1, const float* __restrict__ bh1,
    const float* __restrict__ Wi2, const float* __restrict__ Wh2,
    const float* __restrict__ bi2, const float* __restrict__ bh2,
    const float* __restrict__ Wi3, const float* __restrict__ Wh3,
    const float* __restrict__ bi3, const float* __restrict__ bh3,
    const float* __restrict__ ta1, const float* __restrict__ ta2,
    const float* __restrict__ ta3, const float* __restrict__ tm1,
    const float* __restrict__ tm2, const float* __restrict__ tm3,
    float* __restrict__ dout)
{
    __shared__ __align__(16) float sw[5][H][4];   // 40KB, [mat][k][jl]
    __shared__ float red[4];
    const int tid = threadIdx.x;
    const int b   = tid;
    const int j0  = blockIdx.x * 4;
    const int jgrp = blockIdx.x;

    for (int i = tid; i < 5*H*4; i += 128) {
        int m = i >> 11, rem = i & 2047, k = rem >> 2, jl = rem & 3;
        const float* W = (m==0)?Wh1:(m==1)?Wi2:(m==2)?Wh2:(m==3)?Wi3:Wh3;
        sw[m][k][jl] = W[(size_t)(j0 + jl)*H + k];
    }
    __syncthreads();

    float al1[4], ro1[4], omal1[4], omro1[4];
    float al2[4], ro2[4], omal2[4], omro2[4];
    float al3[4], ro3[4], omal3[4], omro3[4];
    float bh1r[4], bi2r[4], bh2r[4], bi3r[4], bh3r[4];
#pragma unroll
    for (int jl = 0; jl < 4; jl++) {
        int j = j0 + jl;
        al1[jl] = exp_xla_fma(__fdiv_rn(-1.0f, __ldg(&tm1[j])));
        ro1[jl] = exp_xla_fma(__fdiv_rn(-1.0f, __ldg(&ta1[j])));
        al2[jl] = exp_xla_fma(__fdiv_rn(-1.0f, __ldg(&tm2[j])));
        ro2[jl] = exp_xla_fma(__fdiv_rn(-1.0f, __ldg(&ta2[j])));
        al3[jl] = exp_xla_fma(__fdiv_rn(-1.0f, __ldg(&tm3[j])));
        ro3[jl] = exp_xla_fma(__fdiv_rn(-1.0f, __ldg(&ta3[j])));
        omal1[jl] = __fsub_rn(1.0f, al1[jl]); omro1[jl] = __fsub_rn(1.0f, ro1[jl]);
        omal2[jl] = __fsub_rn(1.0f, al2[jl]); omro2[jl] = __fsub_rn(1.0f, ro2[jl]);
        omal3[jl] = __fsub_rn(1.0f, al3[jl]); omro3[jl] = __fsub_rn(1.0f, ro3[jl]);
        bh1r[jl] = __ldg(&bh1[j]);
        bi2r[jl] = __ldg(&bi2[j]); bh2r[jl] = __ldg(&bh2[j]);
        bi3r[jl] = __ldg(&bi3[j]); bh3r[jl] = __ldg(&bh3[j]);
    }

    float m1[4], b1s[4], s1r[4];
    float m2[4], b2s[4], s2r[4];
    float m3[4], b3s[4], s3r[4];
#pragma unroll
    for (int jl = 0; jl < 4; jl++) {
        m1[jl]=0.0f; b1s[jl]=0.01f; s1r[jl]=0.0f;
        m2[jl]=0.0f; b2s[jl]=0.01f; s2r[jl]=0.0f;
        m3[jl]=0.0f; b3s[jl]=0.01f; s3r[jl]=0.0f;
    }

    for (int t = 0; t < T; t++) {
        const int p = t & 1, q = p ^ 1;
        // ---- layer 1 ----
        {
            float r0=0.0f, r1v=0.0f, r2=0.0f, r3=0.0f;
            dot_stream(&g_pb1[p][(size_t)b*128], sw[0], r0, r1v, r2, r3);
            float rr[4] = {r0, r1v, r2, r3};
            unsigned msk = 0;
#pragma unroll
            for (int jl = 0; jl < 4; jl++) {
                int j = j0 + jl;
                float a = __fadd_rn(__fadd_rn(
                    __ldg(&g_xw1[((size_t)t*H + j)*BSZ + b]), rr[jl]), bh1r[jl]);
                ALIF(m1[jl], s1r[jl], b1s[jl], a,
                     al1[jl], omal1[jl], ro1[jl], omro1[jl]);
                if (s1r[jl] != 0.0f) msk |= (1u << jl);
            }
            __stcg(&g_pb1[q][(size_t)b*128 + jgrp], (unsigned char)msk);
        }
        gbar();
        // ---- layer 2 ----
        {
            float ri0=0,ri1=0,ri2=0,ri3=0, rh0=0,rh1=0,rh2=0,rh3=0;
            dot_stream(&g_pb1[q][(size_t)b*128], sw[1], ri0, ri1, ri2, ri3);
            dot_stream(&g_pb2[p][(size_t)b*128], sw[2], rh0, rh1, rh2, rh3);
            float ri[4] = {ri0, ri1, ri2, ri3};
            float rh[4] = {rh0, rh1, rh2, rh3};
            unsigned msk = 0;
#pragma unroll
            for (int jl = 0; jl < 4; jl++) {
                float a = __fadd_rn(__fadd_rn(__fadd_rn(ri[jl], bi2r[jl]),
                                              rh[jl]), bh2r[jl]);
                ALIF(m2[jl], s2r[jl], b2s[jl], a,
                     al2[jl], omal2[jl], ro2[jl], omro2[jl]);
                if (s2r[jl] != 0.0f) msk |= (1u << jl);
            }
            __stcg(&g_pb2[q][(size_t)b*128 + jgrp], (unsigned char)msk);
        }
        gbar();
        // ---- layer 3 ----
        {
            float ri0=0,ri1=0,ri2=0,ri3=0, rh0=0,rh1=0,rh2=0,rh3=0;
            dot_stream(&g_pb2[q][(size_t)b*128], sw[3], ri0, ri1, ri2, ri3);
            dot_stream(&g_pb3[p][(size_t)b*128], sw[4], rh0, rh1, rh2, rh3);
            float ri[4] = {ri0, ri1, ri2, ri3};
            float rh[4] = {rh0, rh1, rh2, rh3};
            unsigned msk = 0;
#pragma unroll
            for (int jl = 0; jl < 4; jl++) {
                int j = j0 + jl;
                float a = __fadd_rn(__fadd_rn(__fadd_rn(ri[jl], bi3r[jl]),
                                              rh[jl]), bh3r[jl]);
                ALIF(m3[jl], s3r[jl], b3s[jl], a,
                     al3[jl], omal3[jl], ro3[jl], omro3[jl]);
                if (s3r[jl] != 0.0f) msk |= (1u << jl);
                g_m3h[((size_t)t*H + j)*BSZ + b] = m3[jl];
                dout[HID_OFF + ((size_t)b*T + t)*H + j] = s3r[jl];
            }
            __stcg(&g_pb3[q][(size_t)b*128 + jgrp], (unsigned char)msk);
        }
        gbar();
    }

    // fire rate: exact integer-valued float sums -> order-independent atomics
    float c = 0.0f;
#pragma unroll
    for (int jl = 0; jl < 4; jl++) c += s1r[jl] + s2r[jl] + s3r[jl];
#pragma unroll
    for (int o = 16; o > 0; o >>= 1) c += __shfl_xor_sync(0xffffffffu, c, o);
    if ((tid & 31) == 0) red[tid >> 5] = c;
    __syncthreads();
    if (tid == 0)
        atomicAdd(&g_cnt, red[0] + red[1] + red[2] + red[3]);
    gbar();
    if (blockIdx.x == 0 && tid == 0)
        dout[FIRE_OFF] = *((volatile float*)&g_cnt) / 196608.0f;
}

// ---------------- kernel: output = (m3@Wo^T chain from 0) + bo ------------
__global__ __launch_bounds__(128) void k_out(const float* __restrict__ Wo,
                                             const float* __restrict__ bo,
                                             float* __restrict__ dout) {
    int t = blockIdx.x, b = threadIdx.x;
    float acc[NOUT];
#pragma unroll
    for (int o = 0; o < NOUT; o++) acc[o] = 0.0f;
    const float* mp = &g_m3h[(size_t)t*H*BSZ + b];
    for (int k = 0; k < H; k++) {
        float v = mp[(size_t)k*BSZ];
#pragma unroll
        for (int o = 0; o < NOUT; o++)
            acc[o] = __fmaf_rn(v, __ldg(&Wo[o*H + k]), acc[o]);
    }
#pragma unroll
    for (int o = 0; o < NOUT; o++)
        dout[((size_t)b*T + t)*NOUT + o] = __fadd_rn(acc[o], __ldg(&bo[o]));
}

// ---------------- launch ---------------------------------------------------
extern "C" void kernel_launch(void* const* d_in, const int* in_sizes, int n_in,
                              void* d_out, int out_size) {
    const float* x      = (const float*)d_in[0];
    const float* W_i2h1 = (const float*)d_in[1];  const float* b_i2h1 = (const float*)d_in[2];
    const float* W_h2h1 = (const float*)d_in[3];  const float* b_h2h1 = (const float*)d_in[4];
    const float* W_i2h2 = (const float*)d_in[5];  const float* b_i2h2 = (const float*)d_in[6];
    const float* W_h2h2 = (const float*)d_in[7];  const float* b_h2h2 = (const float*)d_in[8];
    const float* W_i2h3 = (const float*)d_in[9];  const float* b_i2h3 = (const float*)d_in[10];
    const float* W_h2h3 = (const float*)d_in[11]; const float* b_h2h3 = (const float*)d_in[12];
    const float* W_h2o  = (const float*)d_in[13]; const float* b_h2o  = (const float*)d_in[14];
    const float* ta1 = (const float*)d_in[15];
    const float* ta2 = (const float*)d_in[16];
    const float* ta3 = (const float*)d_in[17];
    const float* tm1 = (const float*)d_in[18];
    const float* tm2 = (const float*)d_in[19];
    const float* tm3 = (const float*)d_in[20];
    float* out = (float*)d_out;

    k_tr  <<<dim3(22, 4, 250), dim3(32, 8)>>>(x);
    k_w1t <<<(INP*H + 255)/256, 256>>>(W_i2h1);
    k_init<<<(2*BSZ*128/4 + 255)/256, 256>>>();
    k_xw1 <<<dim3(4, 250), 256>>>(b_i2h1);

    k_scan<<<NCTA, 128>>>(W_h2h1, b_h2h1,
                          W_i2h2, W_h2h2, b_i2h2, b_h2h2,
                          W_i2h3, W_h2h3, b_i2h3, b_h2h3,
                          ta1, ta2, ta3, tm1, tm2, tm3, out);

    k_out <<<250, 128>>>(W_h2o, b_h2o, out);
}

// round 13
// speedup vs baseline: 7.2567x; 1.1122x over previous
#include <cuda_runtime.h>
#include <math.h>

#define BSZ   128
#define T     250
#define INDIM 700
#define INP   704
#define H     512
#define NOUT  20
#define HB    (H*BSZ)
#define NCTA  128

#define FIRE_OFF (BSZ*T*NOUT)      /* 640000 */
#define HID_OFF  (FIRE_OFF + 1)

// ---------------- device scratch (static, no allocations) ----------------
__device__ __align__(16) float g_xT  [(size_t)T*INP*BSZ];   // x transposed [t][i][b]
__device__ __align__(16) float g_W1T [INP*H];               // W1 transposed [i][j]
__device__ __align__(16) float g_xw1 [(size_t)T*H*BSZ];     // (x@W1^T)+b_i2h1, [t][j][b]
__device__ __align__(16) float g_m3h [(size_t)T*H*BSZ];     // m3 history [t][j][b]
// bit-packed spikes: [slot][b][jg] (byte jg holds spikes of neurons 4jg..4jg+3)
__device__ __align__(16) unsigned char g_pb1[2][BSZ*128];
__device__ __align__(16) unsigned char g_pb2[2][BSZ*128];
__device__ __align__(16) unsigned char g_pb3[2][BSZ*128];
__device__ float    g_cnt;                                  // fire-rate accumulator
__device__ unsigned g_barc;                                 // monotonic barrier counter

// ALIF update with LLVM FPOpFusion::Fast-style contraction (VALIDATED r9-r12).
#define ALIF(mm, ss, bb, hh, al, omal, rr, omrr) do {                      \
    bb = __fmaf_rn(rr, bb, __fmul_rn(omrr, ss));                           \
    float Bth_ = __fmaf_rn(1.8f, bb, 0.01f);                               \
    mm = __fmaf_rn(-Bth_, ss, __fmaf_rn(mm, al, __fmul_rn(omal, hh)));     \
    ss = (__fsub_rn(mm, Bth_) > 0.0f) ? 1.0f : 0.0f;                       \
} while (0)

// XLA:CPU GenerateVF32Exp (VALIDATED r9-r12)
__device__ __forceinline__ float exp_xla_fma(float v) {
    float x = fminf(v, 88.3762626647950f);
    x = fmaxf(x, -88.3762626647949f);
    float fx = floorf(__fmaf_rn(x, 1.44269504088896341f, 0.5f));
    float tmp = __fmul_rn(fx, 0.693359375f);
    float z   = __fmul_rn(fx, -2.12194440e-4f);
    x = __fsub_rn(x, tmp);
    x = __fsub_rn(x, z);
    z = __fmul_rn(x, x);
    float y = 1.9875691500E-4f;
    y = __fmaf_rn(y, x, 1.3981999507E-3f);
    y = __fmaf_rn(y, x, 8.3334519073E-3f);
    y = __fmaf_rn(y, x, 4.1665795894E-2f);
    y = __fmaf_rn(y, x, 1.6666665459E-1f);
    y = __fmaf_rn(y, x, 5.0000001201E-1f);
    y = __fmaf_rn(y, z, x);
    y = __fadd_rn(y, 1.0f);
    int n = (int)fx;
    return __fmul_rn(y, __int_as_float((n + 127) << 23));
}

// packed dual-lane FMA: each lane an independent IEEE fma.rn (bit-exact/lane)
__device__ __forceinline__ void fma2(unsigned long long& r,
                                     unsigned long long a,
                                     unsigned long long b) {
    asm("fma.rn.f32x2 %0, %1, %2, %0;" : "+l"(r) : "l"(a), "l"(b));
}
#define UNPACK2(lo, hi, v) \
    asm("mov.b64 {%0, %1}, %2;" : "=f"(lo), "=f"(hi) : "l"(v))

// grid barrier: monotonic counter
__device__ __forceinline__ void gbar() {
    __syncthreads();
    if (threadIdx.x == 0) {
        __threadfence();
        unsigned r   = atomicAdd(&g_barc, 1u) + 1u;
        unsigned tgt = ((r + NCTA - 1u) / NCTA) * NCTA;
        while (*((volatile unsigned*)&g_barc) < tgt) { }
        __threadfence();
    }
    __syncthreads();
}

// one dot stream over a packed spike vector. Bit-exact vs r12: lane l of the
// f32x2 pair accumulates fma(u, w[k][l], r[l]) in ascending-k order.
__device__ __forceinline__ void dot2(const unsigned char* base,
                                     const float (*swm)[4],
                                     unsigned long long& r01,
                                     unsigned long long& r23) {
    const uint4* mp = (const uint4*)base;
#pragma unroll 1
    for (int wq = 0; wq < 8; wq++) {
        uint4 cur = __ldcg(&mp[wq]);
        unsigned wds[4] = {cur.x, cur.y, cur.z, cur.w};
#pragma unroll
        for (int wi = 0; wi < 4; wi++) {
            unsigned wd = wds[wi];
#pragma unroll
            for (int d = 0; d < 4; d++) {
#pragma unroll
                for (int c = 0; c < 4; c++) {
                    int k = wq*64 + wi*16 + d*4 + c;
                    unsigned long long u2 =
                        (wd & (1u << (8*d + c))) ? 0x3F8000003F800000ULL : 0ULL;
                    ulonglong2 wv = *(const ulonglong2*)&swm[k][0];
                    fma2(r01, u2, wv.x);
                    fma2(r23, u2, wv.y);
                }
            }
        }
    }
}

// ---------------- kernel: transpose x -> g_xT [t][i][b] -------------------
__global__ void k_tr(const float* __restrict__ x) {
    __shared__ float tile[32][33];
    int i0 = blockIdx.x * 32, b0 = blockIdx.y * 32, t = blockIdx.z;
    int tx = threadIdx.x, ty = threadIdx.y;
    int i = i0 + tx;
#pragma unroll
    for (int r = 0; r < 4; r++) {
        int b = b0 + ty + r*8;
        float v = 0.0f;
        if (i < INDIM) v = x[((size_t)b*T + t)*INDIM + i];
        tile[ty + r*8][tx] = v;
    }
    __syncthreads();
#pragma unroll
    for (int r = 0; r < 4; r++) {
        int il = ty + r*8;
        g_xT[((size_t)t*INP + i0 + il)*BSZ + b0 + tx] = tile[tx][il];
    }
}

// ---------------- kernel: transpose W1 -> g_W1T ---------------------------
__global__ void k_w1t(const float* __restrict__ W1) {
    int idx = blockIdx.x * 256 + threadIdx.x;
    if (idx < INP*H) {
        int i = idx >> 9, j = idx & 511;
        g_W1T[idx] = (i < INDIM) ? W1[j*INDIM + i] : 0.0f;
    }
}

// ---------------- kernel: init packed spike buffers + fire counter --------
__global__ void k_init() {
    int idx = blockIdx.x * 256 + threadIdx.x;
    if (idx == 0) g_cnt = 0.0f;
    if (idx < (2*BSZ*128)/4) {
        ((unsigned*)g_pb1)[idx] = 0u;
        ((unsigned*)g_pb2)[idx] = 0u;
        ((unsigned*)g_pb3)[idx] = 0u;
    }
}

// ---------------- kernel: xw1 = (x@W1^T ascending-k chain)+b_i2h1 ---------
// FFMA2 over jx-pairs: lane lo = fma(xf[2p], wf[i], acc_lo) — value-identical
// to the validated r12 chain (operand swap only).
__global__ __launch_bounds__(256) void k_xw1(const float* __restrict__ b1) {
    __shared__ __align__(16) float xs[8*128];
    __shared__ __align__(16) float ws[8*128];
    int jg = blockIdx.x, t = blockIdx.y;
    int tid = threadIdx.x;
    int tx = tid & 15, ty = tid >> 4;

    unsigned long long acc2[8][4];
#pragma unroll
    for (int i = 0; i < 8; i++)
#pragma unroll
        for (int p = 0; p < 4; p++) acc2[i][p] = 0ULL;

    for (int k0 = 0; k0 < INP; k0 += 8) {
#pragma unroll
        for (int r = 0; r < 4; r++) {
            int lin = r*256 + tid;
            int kk = lin >> 7, c = lin & 127;
            xs[lin] = g_xT[((size_t)t*INP + k0 + kk)*BSZ + c];
            ws[lin] = g_W1T[(k0 + kk)*H + jg*128 + c];
        }
        __syncthreads();
#pragma unroll
        for (int kk = 0; kk < 8; kk++) {
            ulonglong2 xa = *(const ulonglong2*)&xs[kk*128 + tx*8];
            ulonglong2 xb = *(const ulonglong2*)&xs[kk*128 + tx*8 + 4];
            unsigned long long xp[4] = {xa.x, xa.y, xb.x, xb.y};
            float4 w0 = *(const float4*)&ws[kk*128 + ty*8];
            float4 w1 = *(const float4*)&ws[kk*128 + ty*8 + 4];
            float wf[8] = {w0.x,w0.y,w0.z,w0.w,w1.x,w1.y,w1.z,w1.w};
#pragma unroll
            for (int i = 0; i < 8; i++) {
                unsigned long long wd2;
                asm("mov.b64 %0, {%1, %1};" : "=l"(wd2) : "f"(wf[i]));
#pragma unroll
                for (int p = 0; p < 4; p++)
                    fma2(acc2[i][p], xp[p], wd2);
            }
        }
        __syncthreads();
    }
#pragma unroll
    for (int i = 0; i < 8; i++) {
        int jcol = jg*128 + ty*8 + i;
        float bias = __ldg(&b1[jcol]);
#pragma unroll
        for (int p = 0; p < 4; p++) {
            float lo, hi;
            UNPACK2(lo, hi, acc2[i][p]);
            g_xw1[((size_t)t*H + jcol)*BSZ + tx*8 + 2*p]     = __fadd_rn(lo, bias);
            g_xw1[((size_t)t*H + jcol)*BSZ + tx*8 + 2*p + 1] = __fadd_rn(hi, bias);
        }
    }
}

// ---------------- persistent pipelined ALIF scan ---------------------------
// 128 CTAs x 128 threads. CTA owns 4 neurons; thread owns batch column b.
// Stage s: l1(t=s) || l2(t=s-1) || l3(t=s-2); ONE grid barrier per stage.
// Slot rule (from r12): layer at step t reads its own buffer slot t&1,
// writes slot (t+1)&1; cross-layer input read at slot (t+1)&1 of the
// producer (written one stage earlier). All stage-s writes read at s+1.
__global__ __launch_bounds__(128) void k_scan(
    const float* __restrict__ Wh1, const float* __restrict__ bh1,
    const float* __restrict__ Wi2, const float* __restrict__ Wh2,
    const float* __restrict__ bi2, const float* __restrict__ bh2,
    const float* __restrict__ Wi3, const float* __restrict__ Wh3,
    const float* __restrict__ bi3, const float* __restrict__ bh3,
    const float* __restrict__ ta1, const float* __restrict__ ta2,
    const float* __restrict__ ta3, const float* __restrict__ tm1,
    const float* __restrict__ tm2, const float* __restrict__ tm3,
    float* __restrict__ dout)
{
    __shared__ __align__(16) float sw[5][H][4];   // 40KB, [mat][k][jl]
    __shared__ float red[4];
    const int tid = threadIdx.x;
    const int b   = tid;
    const int j0  = blockIdx.x * 4;
    const int jgrp = blockIdx.x;

    for (int i = tid; i < 5*H*4; i += 128) {
        int m = i >> 11, rem = i & 2047, k = rem >> 2, jl = rem & 3;
        const float* W = (m==0)?Wh1:(m==1)?Wi2:(m==2)?Wh2:(m==3)?Wi3:Wh3;
        sw[m][k][jl] = W[(size_t)(j0 + jl)*H + k];
    }
    __syncthreads();

    float al1[4], ro1[4], omal1[4], omro1[4];
    float al2[4], ro2[4], omal2[4], omro2[4];
    float al3[4], ro3[4], omal3[4], omro3[4];
    float bh1r[4], bi2r[4], bh2r[4], bi3r[4], bh3r[4];
#pragma unroll
    for (int jl = 0; jl < 4; jl++) {
        int j = j0 + jl;
        al1[jl] = exp_xla_fma(__fdiv_rn(-1.0f, __ldg(&tm1[j])));
        ro1[jl] = exp_xla_fma(__fdiv_rn(-1.0f, __ldg(&ta1[j])));
        al2[jl] = exp_xla_fma(__fdiv_rn(-1.0f, __ldg(&tm2[j])));
        ro2[jl] = exp_xla_fma(__fdiv_rn(-1.0f, __ldg(&ta2[j])));
        al3[jl] = exp_xla_fma(__fdiv_rn(-1.0f, __ldg(&tm3[j])));
        ro3[jl] = exp_xla_fma(__fdiv_rn(-1.0f, __ldg(&ta3[j])));
        omal1[jl] = __fsub_rn(1.0f, al1[jl]); omro1[jl] = __fsub_rn(1.0f, ro1[jl]);
        omal2[jl] = __fsub_rn(1.0f, al2[jl]); omro2[jl] = __fsub_rn(1.0f, ro2[jl]);
        omal3[jl] = __fsub_rn(1.0f, al3[jl]); omro3[jl] = __fsub_rn(1.0f, ro3[jl]);
        bh1r[jl] = __ldg(&bh1[j]);
        bi2r[jl] = __ldg(&bi2[j]); bh2r[jl] = __ldg(&bh2[j]);
        bi3r[jl] = __ldg(&bi3[j]); bh3r[jl] = __ldg(&bh3[j]);
    }

    float m1[4], b1s[4], s1r[4];
    float m2[4], b2s[4], s2r[4];
    float m3[4], b3s[4], s3r[4];
#pragma unroll
    for (int jl = 0; jl < 4; jl++) {
        m1[jl]=0.0f; b1s[jl]=0.01f; s1r[jl]=0.0f;
        m2[jl]=0.0f; b2s[jl]=0.01f; s2r[jl]=0.0f;
        m3[jl]=0.0f; b3s[jl]=0.01f; s3r[jl]=0.0f;
    }

    for (int s = 0; s < T + 2; s++) {
        // ---- layer 1: t = s ----
        if (s < T) {
            const int t = s;
            unsigned long long r01 = 0ULL, r23 = 0ULL;
            dot2(&g_pb1[t & 1][(size_t)b*128], sw[0], r01, r23);
            float rr[4];
            UNPACK2(rr[0], rr[1], r01);
            UNPACK2(rr[2], rr[3], r23);
            unsigned msk = 0;
#pragma unroll
            for (int jl = 0; jl < 4; jl++) {
                int j = j0 + jl;
                float a = __fadd_rn(__fadd_rn(
                    __ldg(&g_xw1[((size_t)t*H + j)*BSZ + b]), rr[jl]), bh1r[jl]);
                ALIF(m1[jl], s1r[jl], b1s[jl], a,
                     al1[jl], omal1[jl], ro1[jl], omro1[jl]);
                if (s1r[jl] != 0.0f) msk |= (1u << jl);
            }
            __stcg(&g_pb1[(t+1) & 1][(size_t)b*128 + jgrp], (unsigned char)msk);
        }
        // ---- layer 2: t = s-1 ----
        if (s >= 1 && s <= T) {
            const int t = s - 1;
            unsigned long long i01 = 0ULL, i23 = 0ULL, h01 = 0ULL, h23 = 0ULL;
            dot2(&g_pb1[(t+1) & 1][(size_t)b*128], sw[1], i01, i23);
            dot2(&g_pb2[t & 1][(size_t)b*128],     sw[2], h01, h23);
            float ri[4], rh[4];
            UNPACK2(ri[0], ri[1], i01); UNPACK2(ri[2], ri[3], i23);
            UNPACK2(rh[0], rh[1], h01); UNPACK2(rh[2], rh[3], h23);
            unsigned msk = 0;
#pragma unroll
            for (int jl = 0; jl < 4; jl++) {
                float a = __fadd_rn(__fadd_rn(__fadd_rn(ri[jl], bi2r[jl]),
                                              rh[jl]), bh2r[jl]);
                ALIF(m2[jl], s2r[jl], b2s[jl], a,
                     al2[jl], omal2[jl], ro2[jl], omro2[jl]);
                if (s2r[jl] != 0.0f) msk |= (1u << jl);
            }
            __stcg(&g_pb2[(t+1) & 1][(size_t)b*128 + jgrp], (unsigned char)msk);
        }
        // ---- layer 3: t = s-2 ----
        if (s >= 2) {
            const int t = s - 2;
            unsigned long long i01 = 0ULL, i23 = 0ULL, h01 = 0ULL, h23 = 0ULL;
            dot2(&g_pb2[(t+1) & 1][(size_t)b*128], sw[3], i01, i23);
            dot2(&g_pb3[t & 1][(size_t)b*128],     sw[4], h01, h23);
            float ri[4], rh[4];
            UNPACK2(ri[0], ri[1], i01); UNPACK2(ri[2], ri[3], i23);
            UNPACK2(rh[0], rh[1], h01); UNPACK2(rh[2], rh[3], h23);
            unsigned msk = 0;
#pragma unroll
            for (int jl = 0; jl < 4; jl++) {
                int j = j0 + jl;
                float a = __fadd_rn(__fadd_rn(__fadd_rn(ri[jl], bi3r[jl]),
                                              rh[jl]), bh3r[jl]);
                ALIF(m3[jl], s3r[jl], b3s[jl], a,
                     al3[jl], omal3[jl], ro3[jl], omro3[jl]);
                if (s3r[jl] != 0.0f) msk |= (1u << jl);
                g_m3h[((size_t)t*H + j)*BSZ + b] = m3[jl];
                dout[HID_OFF + ((size_t)b*T + t)*H + j] = s3r[jl];
            }
            __stcg(&g_pb3[(t+1) & 1][(size_t)b*128 + jgrp], (unsigned char)msk);
        }
        gbar();
    }

    // fire rate: exact integer-valued float sums -> order-independent atomics
    float c = 0.0f;
#pragma unroll
    for (int jl = 0; jl < 4; jl++) c += s1r[jl] + s2r[jl] + s3r[jl];
#pragma unroll
    for (int o = 16; o > 0; o >>= 1) c += __shfl_xor_sync(0xffffffffu, c, o);
    if ((tid & 31) == 0) red[tid >> 5] = c;
    __syncthreads();
    if (tid == 0)
        atomicAdd(&g_cnt, red[0] + red[1] + red[2] + red[3]);
    gbar();
    if (blockIdx.x == 0 && tid == 0)
        dout[FIRE_OFF] = *((volatile float*)&g_cnt) / 196608.0f;
}

// ---------------- kernel: output = (m3@Wo^T chain from 0) + bo ------------
__global__ __launch_bounds__(128) void k_out(const float* __restrict__ Wo,
                                             const float* __restrict__ bo,
                                             float* __restrict__ dout) {
    int t = blockIdx.x, b = threadIdx.x;
    float acc[NOUT];
#pragma unroll
    for (int o = 0; o < NOUT; o++) acc[o] = 0.0f;
    const float* mp = &g_m3h[(size_t)t*H*BSZ + b];
    for (int k = 0; k < H; k++) {
        float v = mp[(size_t)k*BSZ];
#pragma unroll
        for (int o = 0; o < NOUT; o++)
            acc[o] = __fmaf_rn(v, __ldg(&Wo[o*H + k]), acc[o]);
    }
#pragma unroll
    for (int o = 0; o < NOUT; o++)
        dout[((size_t)b*T + t)*NOUT + o] = __fadd_rn(acc[o], __ldg(&bo[o]));
}

// ---------------- launch ---------------------------------------------------
extern "C" void kernel_launch(void* const* d_in, const int* in_sizes, int n_in,
                              void* d_out, int out_size) {
    const float* x      = (const float*)d_in[0];
    const float* W_i2h1 = (const float*)d_in[1];  const float* b_i2h1 = (const float*)d_in[2];
    const float* W_h2h1 = (const float*)d_in[3];  const float* b_h2h1 = (const float*)d_in[4];
    const float* W_i2h2 = (const float*)d_in[5];  const float* b_i2h2 = (const float*)d_in[6];
    const float* W_h2h2 = (const float*)d_in[7];  const float* b_h2h2 = (const float*)d_in[8];
    const float* W_i2h3 = (const float*)d_in[9];  const float* b_i2h3 = (const float*)d_in[10];
    const float* W_h2h3 = (const float*)d_in[11]; const float* b_h2h3 = (const float*)d_in[12];
    const float* W_h2o  = (const float*)d_in[13]; const float* b_h2o  = (const float*)d_in[14];
    const float* ta1 = (const float*)d_in[15];
    const float* ta2 = (const float*)d_in[16];
    const float* ta3 = (const float*)d_in[17];
    const float* tm1 = (const float*)d_in[18];
    const float* tm2 = (const float*)d_in[19];
    const float* tm3 = (const float*)d_in[20];
    float* out = (float*)d_out;

    k_tr  <<<dim3(22, 4, 250), dim3(32, 8)>>>(x);
    k_w1t <<<(INP*H + 255)/256, 256>>>(W_i2h1);
    k_init<<<(2*BSZ*128/4 + 255)/256, 256>>>();
    k_xw1 <<<dim3(4, 250), 256>>>(b_i2h1);

    k_scan<<<NCTA, 128>>>(W_h2h1, b_h2h1,
                          W_i2h2, W_h2h2, b_i2h2, b_h2h2,
                          W_i2h3, W_h2h3, b_i2h3, b_h2h3,
                          ta1, ta2, ta3, tm1, tm2, tm3, out);

    k_out <<<250, 128>>>(W_h2o, b_h2o, out);
}